// round 14
// baseline (speedup 1.0000x reference)
#include <cuda_runtime.h>
#include <cuda_bf16.h>
#include <cstdint>

#define Bb 4
#define Tt 4096
#define Cc 1024
#define Hh 64

// combined scale: softmax(QK^T /64); exp(x/64) = exp2(x * log2e/64)
#define S2L2E 0.022542110f

#define CHUNK 8
#define MAXC 8
#define NPCH 151   // sum over pairs p=0..31 of ceil(min(2p+3,64)/8)

// packed bf16x2 (h-pairs) hi/lo images of Q,K,V: [B*T][32] words
__device__ uint32_t g_Qh[Bb * Tt * 32];
__device__ uint32_t g_Ql[Bb * Tt * 32];
__device__ uint32_t g_Kh[Bb * Tt * 32];
__device__ uint32_t g_Kl[Bb * Tt * 32];
__device__ uint32_t g_Vh[Bb * Tt * 32];
__device__ uint32_t g_Vl[Bb * Tt * 32];

// pre-converted weights: [3][64 rows][512 words]
__device__ uint32_t g_Wh[3][64 * 512];
__device__ uint32_t g_Wl[3][64 * 512];

// split-KV partials (unnormalized O and plain sums l; fixed softmax base 0)
__device__ float g_Opart[Bb * 64 * MAXC * 64 * 64];
__device__ float g_Lpart[Bb * 64 * MAXC * 64];

// ---------------------------------------------------------------------------
__device__ __forceinline__ void mma_bf16(float c[4], uint32_t a0, uint32_t a1,
                                         uint32_t a2, uint32_t a3,
                                         uint32_t b0, uint32_t b1) {
    asm volatile(
        "mma.sync.aligned.m16n8k16.row.col.f32.bf16.bf16.f32 "
        "{%0,%1,%2,%3}, {%4,%5,%6,%7}, {%8,%9}, {%0,%1,%2,%3};"
        : "+f"(c[0]), "+f"(c[1]), "+f"(c[2]), "+f"(c[3])
        : "r"(a0), "r"(a1), "r"(a2), "r"(a3), "r"(b0), "r"(b1));
}

__device__ __forceinline__ void ldmatrix_x4_trans(uint32_t& r0, uint32_t& r1,
                                                  uint32_t& r2, uint32_t& r3,
                                                  uint32_t addr) {
    asm volatile(
        "ldmatrix.sync.aligned.m8n8.x4.trans.shared.b16 {%0,%1,%2,%3}, [%4];"
        : "=r"(r0), "=r"(r1), "=r"(r2), "=r"(r3) : "r"(addr));
}

__device__ __forceinline__ float ex2(float x) {
    float r;
    asm("ex2.approx.ftz.f32 %0, %1;" : "=f"(r) : "f"(x));
    return r;
}

__device__ __forceinline__ uint32_t packbf(float a, float b) {
    __nv_bfloat162 t;
    t.x = __float2bfloat16(a);
    t.y = __float2bfloat16(b);
    return *reinterpret_cast<uint32_t*>(&t);
}

__device__ __forceinline__ void cvt_hilo(float2 v, uint32_t& hi, uint32_t& lo) {
    asm("cvt.rn.bf16x2.f32 %0, %1, %2;" : "=r"(hi) : "f"(v.y), "f"(v.x));
    __nv_bfloat162 h = *reinterpret_cast<__nv_bfloat162*>(&hi);
    float lx = v.x - __bfloat162float(h.x);
    float ly = v.y - __bfloat162float(h.y);
    asm("cvt.rn.bf16x2.f32 %0, %1, %2;" : "=r"(lo) : "f"(ly), "f"(lx));
}

__device__ __forceinline__ void cp16(uint32_t saddr, const void* gaddr) {
    asm volatile("cp.async.cg.shared.global [%0], [%1], 16;"
                 :: "r"(saddr), "l"(gaddr) : "memory");
}
#define CP_COMMIT() asm volatile("cp.async.commit_group;" ::: "memory")
#define CP_WAIT0()  asm volatile("cp.async.wait_group 0;" ::: "memory")

__device__ __forceinline__ uint32_t smem_u32(const void* p) {
    uint32_t a;
    asm("{ .reg .u64 t; cvta.to.shared.u64 t, %1; cvt.u32.u64 %0, t; }"
        : "=r"(a) : "l"(p));
    return a;
}

#define LDF 72   // fp32 row stride for proj X smem
#define LWW 36   // uint32 (bf16x2) row stride (=144B)

// ===========================================================================
// Pre-convert W matrices to bf16 hi/lo packed images.
// ===========================================================================
__global__ __launch_bounds__(128) void wcvt_kernel(
    const float* __restrict__ Wq, const float* __restrict__ Wk,
    const float* __restrict__ Wv)
{
    const int z = blockIdx.y;
    const float* W = (z == 0) ? Wq : (z == 1) ? Wk : Wv;
    uint32_t* outh = g_Wh[z];
    uint32_t* outl = g_Wl[z];
    const int base = blockIdx.x * 2048;
    for (int i = threadIdx.x; i < 2048; i += 128) {
        int w = base + i;
        float2 v = *(const float2*)&W[(long)w * 2];
        uint32_t hi, lo;
        cvt_hilo(v, hi, lo);
        outh[w] = hi;
        outl[w] = lo;
    }
}

// ===========================================================================
// Projection, 256 threads: 8 warps, N split in halves (warps 0-3 cols 0-31,
// warps 4-7 cols 32-63) over shared X/W smem. M=64 per CTA.
// ===========================================================================
struct PBuf {
    float Xs[64][LDF];         // 18432 B
    uint32_t Whs[64][LWW];     //  9216 B
    uint32_t Wls[64][LWW];     //  9216 B
};                             // 36864 B; x2 = 73728 B

__global__ __launch_bounds__(256, 2) void proj_kernel(
    const float* __restrict__ xq, const float* __restrict__ xk,
    const float* __restrict__ xv)
{
    extern __shared__ char smraw[];
    PBuf* buf = reinterpret_cast<PBuf*>(smraw);

    const float* x;
    const uint32_t* Wh;
    const uint32_t* Wl;
    uint32_t* outh;
    uint32_t* outl;
    if (blockIdx.z == 0)      { x = xq; Wh = g_Wh[0]; Wl = g_Wl[0]; outh = g_Qh; outl = g_Ql; }
    else if (blockIdx.z == 1) { x = xk; Wh = g_Wh[1]; Wl = g_Wl[1]; outh = g_Kh; outl = g_Kl; }
    else                      { x = xv; Wh = g_Wh[2]; Wl = g_Wl[2]; outh = g_Vh; outl = g_Vl; }

    const int tid = threadIdx.x;
    const int warp = tid >> 5;
    const int lane = tid & 31;
    const int lr = lane >> 2;
    const int ql = lane & 3;
    const int nh = warp >> 2;      // n half: 0 or 1
    const int mw = warp & 3;       // m fragment
    const long row0 = (long)blockIdx.x * 64;

    float acc[4][4];
#pragma unroll
    for (int n = 0; n < 4; n++)
#pragma unroll
        for (int e = 0; e < 4; e++) acc[n][e] = 0.f;

    {
        const uint32_t xb = smem_u32(&buf[0].Xs[0][0]);
        const uint32_t whb = smem_u32(&buf[0].Whs[0][0]);
        const uint32_t wlb = smem_u32(&buf[0].Wls[0][0]);
#pragma unroll
        for (int i = 0; i < 4; i++) {       // X: 1024 16B segs
            int idx = tid + i * 256;
            int r = idx >> 4, seg = idx & 15;
            cp16(xb + (uint32_t)(r * LDF + seg * 4) * 4,
                 &x[(row0 + r) * Cc + 0 + seg * 4]);
        }
#pragma unroll
        for (int i = 0; i < 2; i++) {       // W hi/lo: 512 segs each
            int idx = tid + i * 256;
            int r = idx >> 3, seg = idx & 7;
            uint32_t soff = (uint32_t)(r * LWW + seg * 4) * 4;
            cp16(whb + soff, &Wh[(long)r * 512 + 0 + seg * 4]);
            cp16(wlb + soff, &Wl[(long)r * 512 + 0 + seg * 4]);
        }
        CP_COMMIT();
    }

    for (int chunk = 0; chunk < 16; chunk++) {
        const PBuf& cur = buf[chunk & 1];
        CP_WAIT0();
        __syncthreads();

        if (chunk < 15) {
            const int k0 = (chunk + 1) * 64;
            const int w0 = (chunk + 1) * 32;
            PBuf& nxt = buf[(chunk + 1) & 1];
            const uint32_t xb = smem_u32(&nxt.Xs[0][0]);
            const uint32_t whb = smem_u32(&nxt.Whs[0][0]);
            const uint32_t wlb = smem_u32(&nxt.Wls[0][0]);
#pragma unroll
            for (int i = 0; i < 4; i++) {
                int idx = tid + i * 256;
                int r = idx >> 4, seg = idx & 15;
                cp16(xb + (uint32_t)(r * LDF + seg * 4) * 4,
                     &x[(row0 + r) * Cc + k0 + seg * 4]);
            }
#pragma unroll
            for (int i = 0; i < 2; i++) {
                int idx = tid + i * 256;
                int r = idx >> 3, seg = idx & 7;
                uint32_t soff = (uint32_t)(r * LWW + seg * 4) * 4;
                cp16(whb + soff, &Wh[(long)r * 512 + w0 + seg * 4]);
                cp16(wlb + soff, &Wl[(long)r * 512 + w0 + seg * 4]);
            }
            CP_COMMIT();
        }

#pragma unroll
        for (int s = 0; s < 4; s++) {
            const int kk = s * 16 + ql * 2;
            const int rr = mw * 16 + lr;
            uint32_t ah0, ah1, ah2, ah3, al0, al1, al2, al3;
            cvt_hilo(*(const float2*)&cur.Xs[rr][kk],         ah0, al0);
            cvt_hilo(*(const float2*)&cur.Xs[rr + 8][kk],     ah1, al1);
            cvt_hilo(*(const float2*)&cur.Xs[rr][kk + 8],     ah2, al2);
            cvt_hilo(*(const float2*)&cur.Xs[rr + 8][kk + 8], ah3, al3);
#pragma unroll
            for (int n = 0; n < 4; n++) {
                const int wn = nh * 4 + n;
                const int ww = (wn * 8 + lr) * LWW + 8 * s + ql;
                uint32_t bh0 = cur.Whs[0][ww];
                uint32_t bh1 = cur.Whs[0][ww + 4];
                uint32_t bl0 = cur.Wls[0][ww];
                uint32_t bl1 = cur.Wls[0][ww + 4];
                mma_bf16(acc[n], ah0, ah1, ah2, ah3, bh0, bh1);
                mma_bf16(acc[n], ah0, ah1, ah2, ah3, bl0, bl1);
                mma_bf16(acc[n], al0, al1, al2, al3, bh0, bh1);
            }
        }
        __syncthreads();
    }

    // epilogue: write packed bf16 hi/lo images
    {
        long rr = row0 + mw * 16 + lr;
#pragma unroll
        for (int n = 0; n < 4; n++) {
            int wn = nh * 4 + n;
            int wcol = 4 * wn + ql;
            uint32_t h0, l0, h1, l1;
            cvt_hilo(make_float2(acc[n][0], acc[n][1]), h0, l0);
            cvt_hilo(make_float2(acc[n][2], acc[n][3]), h1, l1);
            outh[rr * 32 + wcol] = h0;
            outl[rr * 32 + wcol] = l0;
            outh[(rr + 8) * 32 + wcol] = h1;
            outl[(rr + 8) * 32 + wcol] = l1;
        }
    }
}

// ===========================================================================
// Phase 1: split-KV flash attention, 256 threads: warp-group g (warps 4g..4g+3)
// serves q-tile 2p+g; both groups share the K/V smem stream. Fixed softmax
// base 0; even tile's out-of-range tail is fully masked -> exact zeros.
// ===========================================================================
struct ABuf {
    uint32_t Kh[64 * LWW];
    uint32_t Kl[64 * LWW];
    uint32_t Vh[64 * LWW];
    uint32_t Vl[64 * LWW];
};                           // 36864 B; x2 = 73728 B

__device__ __forceinline__ void load_tile(uint32_t dstbase,
                                          const uint32_t* __restrict__ src,
                                          long rowbase, int tid) {
#pragma unroll
    for (int i = 0; i < 2; i++) {
        int idx = tid + i * 256;
        int r = idx >> 3, seg = idx & 7;
        cp16(dstbase + (uint32_t)(r * LWW + seg * 4) * 4,
             &src[(rowbase + r) * 32 + seg * 4]);
    }
}

__global__ __launch_bounds__(256, 2) void attn_kernel()
{
    extern __shared__ char smraw2[];
    ABuf* bufs = reinterpret_cast<ABuf*>(smraw2);

    const int tid = threadIdx.x;
    const int warp = tid >> 5;
    const int lane = tid & 31;
    const int lr = lane >> 2;
    const int lc = (lane & 3) * 2;
    const int ql = lane & 3;
    const int g = warp >> 2;       // q-tile group
    const int wq = warp & 3;       // m fragment within group
    const int bb = blockIdx.y;

    // decode (pair p, chunk c)
    int rem = blockIdx.x;
    int p = 0;
#pragma unroll 1
    for (; p < 32; p++) {
        int cov = min(2 * p + 3, 64);
        int nc = (cov + 7) >> 3;
        if (rem < nc) break;
        rem -= nc;
    }
    const int c = rem;
    const int cov = min(2 * p + 3, 64);
    const int tstart = c * CHUNK;
    const int tend = min(tstart + CHUNK, cov);
    const int tq = 2 * p + g;
    const int q0 = tq * 64;

    const long brow = (long)bb * Tt;

    // issue first K/V tile
    {
        const long j0 = (long)tstart * 64;
        load_tile(smem_u32(bufs[0].Kh), g_Kh, brow + j0, tid);
        load_tile(smem_u32(bufs[0].Kl), g_Kl, brow + j0, tid);
        load_tile(smem_u32(bufs[0].Vh), g_Vh, brow + j0, tid);
        load_tile(smem_u32(bufs[0].Vl), g_Vl, brow + j0, tid);
        CP_COMMIT();
    }

    const int qrow = wq * 16 + lr;

    // Q fragments: direct global loads (once per CTA; L2-resident)
    uint32_t qah[4][4], qal[4][4];
    {
        const long qg0 = (brow + q0 + qrow) * 32;
        const long qg8 = qg0 + 8 * 32;
#pragma unroll
        for (int s = 0; s < 4; s++) {
            const int col = 8 * s + ql;
            qah[s][0] = g_Qh[qg0 + col];
            qah[s][1] = g_Qh[qg8 + col];
            qah[s][2] = g_Qh[qg0 + col + 4];
            qah[s][3] = g_Qh[qg8 + col + 4];
            qal[s][0] = g_Ql[qg0 + col];
            qal[s][1] = g_Ql[qg8 + col];
            qal[s][2] = g_Ql[qg0 + col + 4];
            qal[s][3] = g_Ql[qg8 + col + 4];
        }
    }

    float l0 = 0.f, l1 = 0.f;
    float oacc[8][4];
#pragma unroll
    for (int n = 0; n < 8; n++)
#pragma unroll
        for (int e = 0; e < 4; e++) oacc[n][e] = 0.f;

    const uint32_t vofs = (uint32_t)((((lane >> 3) & 1) * 8 + (lane & 7)) * 144 +
                                     ((lane >> 4) * 16));

    for (int t = tstart; t < tend; t++) {
        const int j0 = t * 64;
        const ABuf& cur = bufs[(t - tstart) & 1];
        CP_WAIT0();
        __syncthreads();

        if (t + 1 < tend) {
            const long j1 = (long)(t + 1) * 64;
            ABuf& nxt = bufs[(t + 1 - tstart) & 1];
            load_tile(smem_u32(nxt.Kh), g_Kh, brow + j1, tid);
            load_tile(smem_u32(nxt.Kl), g_Kl, brow + j1, tid);
            load_tile(smem_u32(nxt.Vh), g_Vh, brow + j1, tid);
            load_tile(smem_u32(nxt.Vl), g_Vl, brow + j1, tid);
            CP_COMMIT();
        }

        // ---- S = Q K^T (bf16x3) ----
        float sc[8][4];
#pragma unroll
        for (int n = 0; n < 8; n++)
#pragma unroll
            for (int e = 0; e < 4; e++) sc[n][e] = 0.f;
#pragma unroll
        for (int s = 0; s < 4; s++) {
#pragma unroll
            for (int n = 0; n < 8; n++) {
                const int kw = (n * 8 + lr) * LWW + 8 * s + ql;
                uint32_t bh0 = cur.Kh[kw];
                uint32_t bh1 = cur.Kh[kw + 4];
                uint32_t bl0 = cur.Kl[kw];
                uint32_t bl1 = cur.Kl[kw + 4];
                mma_bf16(sc[n], qah[s][0], qah[s][1], qah[s][2], qah[s][3], bh0, bh1);
                mma_bf16(sc[n], qah[s][0], qah[s][1], qah[s][2], qah[s][3], bl0, bl1);
                mma_bf16(sc[n], qal[s][0], qal[s][1], qal[s][2], qal[s][3], bh0, bh1);
            }
        }

        // ---- causal mask (diag offset +1) ----
        if (j0 >= q0) {
            const int i0 = q0 + qrow;
#pragma unroll
            for (int n = 0; n < 8; n++) {
                int j = j0 + n * 8 + lc;
                if (j     > i0 + 1) sc[n][0] = -3.0e38f;
                if (j + 1 > i0 + 1) sc[n][1] = -3.0e38f;
                if (j     > i0 + 9) sc[n][2] = -3.0e38f;
                if (j + 1 > i0 + 9) sc[n][3] = -3.0e38f;
            }
        }

        // ---- softmax numerator, fixed base 0 ----
        float ps0 = 0.f, ps1 = 0.f;
#pragma unroll
        for (int n = 0; n < 8; n++) {
            sc[n][0] = ex2(sc[n][0] * S2L2E);
            sc[n][1] = ex2(sc[n][1] * S2L2E);
            sc[n][2] = ex2(sc[n][2] * S2L2E);
            sc[n][3] = ex2(sc[n][3] * S2L2E);
            ps0 += sc[n][0] + sc[n][1];
            ps1 += sc[n][2] + sc[n][3];
        }
        ps0 += __shfl_xor_sync(0xffffffffu, ps0, 1);
        ps0 += __shfl_xor_sync(0xffffffffu, ps0, 2);
        ps1 += __shfl_xor_sync(0xffffffffu, ps1, 1);
        ps1 += __shfl_xor_sync(0xffffffffu, ps1, 2);
        l0 += ps0;
        l1 += ps1;

        // ---- O += P V (bf16x3) ----
        const uint32_t vhb = smem_u32(cur.Vh) + vofs;
        const uint32_t vlb = smem_u32(cur.Vl) + vofs;
#pragma unroll
        for (int s = 0; s < 4; s++) {
            const int t0 = 2 * s, t1 = 2 * s + 1;
            uint32_t ph0 = packbf(sc[t0][0], sc[t0][1]);
            uint32_t ph1 = packbf(sc[t0][2], sc[t0][3]);
            uint32_t ph2 = packbf(sc[t1][0], sc[t1][1]);
            uint32_t ph3 = packbf(sc[t1][2], sc[t1][3]);
            __nv_bfloat162* hp;
            uint32_t pl0, pl1, pl2, pl3;
            hp = (__nv_bfloat162*)&ph0;
            pl0 = packbf(sc[t0][0] - __bfloat162float(hp->x),
                         sc[t0][1] - __bfloat162float(hp->y));
            hp = (__nv_bfloat162*)&ph1;
            pl1 = packbf(sc[t0][2] - __bfloat162float(hp->x),
                         sc[t0][3] - __bfloat162float(hp->y));
            hp = (__nv_bfloat162*)&ph2;
            pl2 = packbf(sc[t1][0] - __bfloat162float(hp->x),
                         sc[t1][1] - __bfloat162float(hp->y));
            hp = (__nv_bfloat162*)&ph3;
            pl3 = packbf(sc[t1][2] - __bfloat162float(hp->x),
                         sc[t1][3] - __bfloat162float(hp->y));
            const uint32_t sb = (uint32_t)(s * 2304);
#pragma unroll
            for (int np = 0; np < 4; np++) {
                uint32_t bh0, bh1, bh2, bh3, bl0, bl1, bl2, bl3;
                ldmatrix_x4_trans(bh0, bh1, bh2, bh3, vhb + sb + np * 32);
                ldmatrix_x4_trans(bl0, bl1, bl2, bl3, vlb + sb + np * 32);
                mma_bf16(oacc[2 * np],     ph0, ph1, ph2, ph3, bh0, bh1);
                mma_bf16(oacc[2 * np],     ph0, ph1, ph2, ph3, bl0, bl1);
                mma_bf16(oacc[2 * np],     pl0, pl1, pl2, pl3, bh0, bh1);
                mma_bf16(oacc[2 * np + 1], ph0, ph1, ph2, ph3, bh2, bh3);
                mma_bf16(oacc[2 * np + 1], ph0, ph1, ph2, ph3, bl2, bl3);
                mma_bf16(oacc[2 * np + 1], pl0, pl1, pl2, pl3, bh2, bh3);
            }
        }
        __syncthreads();
    }

    const long pbase = (((long)bb * 64 + tq) * MAXC + c) * 64;
    float* Op = g_Opart + pbase * 64;
#pragma unroll
    for (int n = 0; n < 8; n++) {
        int col = n * 8 + lc;
        *(float2*)&Op[(long)qrow * 64 + col] = make_float2(oacc[n][0], oacc[n][1]);
        *(float2*)&Op[(long)(qrow + 8) * 64 + col] = make_float2(oacc[n][2], oacc[n][3]);
    }
    if ((lane & 3) == 0) {
        g_Lpart[pbase + qrow] = l0;
        g_Lpart[pbase + qrow + 8] = l1;
    }
}

// ===========================================================================
// Phase 2: merge = plain sums over the PAIRED chunk count (extra chunk of an
// even q-tile is all zeros and contributes nothing).
// ===========================================================================
__global__ __launch_bounds__(512) void merge_kernel(float* __restrict__ out)
{
    const int tid = threadIdx.x;
    const int r = tid >> 3;
    const int cg = (tid & 7) * 8;
    const int tq = blockIdx.x;
    const int bb = blockIdx.y;

    const int cov = min((tq | 1) + 2, 64);
    const int nc = (cov + 7) >> 3;
    const long base = ((long)bb * 64 + tq) * MAXC;

    float acc[8];
#pragma unroll
    for (int i = 0; i < 8; i++) acc[i] = 0.f;
    float ltot = 0.f;

    for (int c = 0; c < nc; c++) {
        ltot += g_Lpart[(base + c) * 64 + r];
        const float* Op = g_Opart + ((base + c) * 64 + r) * 64 + cg;
        float4 v0 = *(const float4*)&Op[0];
        float4 v1 = *(const float4*)&Op[4];
        acc[0] += v0.x; acc[1] += v0.y; acc[2] += v0.z; acc[3] += v0.w;
        acc[4] += v1.x; acc[5] += v1.y; acc[6] += v1.z; acc[7] += v1.w;
    }

    const float inv = 1.0f / ltot;
    float* orow = out + ((long)bb * Tt + tq * 64 + r) * Hh + cg;
    float4 o0, o1;
    o0.x = acc[0] * inv; o0.y = acc[1] * inv;
    o0.z = acc[2] * inv; o0.w = acc[3] * inv;
    o1.x = acc[4] * inv; o1.y = acc[5] * inv;
    o1.z = acc[6] * inv; o1.w = acc[7] * inv;
    *(float4*)&orow[0] = o0;
    *(float4*)&orow[4] = o1;
}

// ===========================================================================
extern "C" void kernel_launch(void* const* d_in, const int* in_sizes, int n_in,
                              void* d_out, int out_size)
{
    const float* q  = (const float*)d_in[0];
    const float* k  = (const float*)d_in[1];
    const float* v  = (const float*)d_in[2];
    const float* Wq = (const float*)d_in[3];
    const float* Wk = (const float*)d_in[4];
    const float* Wv = (const float*)d_in[5];
    float* out = (float*)d_out;

    cudaFuncSetAttribute(proj_kernel,
                         cudaFuncAttributeMaxDynamicSharedMemorySize,
                         (int)(2 * sizeof(PBuf)));
    cudaFuncSetAttribute(attn_kernel,
                         cudaFuncAttributeMaxDynamicSharedMemorySize,
                         (int)(2 * sizeof(ABuf)));

    wcvt_kernel<<<dim3(16, 3), 128>>>(Wq, Wk, Wv);
    dim3 pgrid((Bb * Tt) / 64, 1, 3);
    proj_kernel<<<pgrid, 256, 2 * sizeof(PBuf)>>>(q, k, v);
    attn_kernel<<<dim3(NPCH, Bb), 256, 2 * sizeof(ABuf)>>>();
    merge_kernel<<<dim3(Tt / 64, Bb), 512>>>(out);
}

// round 16
// speedup vs baseline: 1.0841x; 1.0841x over previous
#include <cuda_runtime.h>
#include <cuda_bf16.h>
#include <cstdint>

#define Bb 4
#define Tt 4096
#define Cc 1024
#define Hh 64

// combined scale: softmax(QK^T /64); exp(x/64) = exp2(x * log2e/64)
#define S2L2E 0.022542110f

#define CHUNK 8
#define MAXC 8
#define NCHUNKS 295

// packed bf16x2 (h-pairs) hi/lo images of Q,K,V: [B*T][32] words
__device__ uint32_t g_Qh[Bb * Tt * 32];
__device__ uint32_t g_Ql[Bb * Tt * 32];
__device__ uint32_t g_Kh[Bb * Tt * 32];
__device__ uint32_t g_Kl[Bb * Tt * 32];
__device__ uint32_t g_Vh[Bb * Tt * 32];
__device__ uint32_t g_Vl[Bb * Tt * 32];

// pre-converted weights: [3][64 rows][512 words]
__device__ uint32_t g_Wh[3][64 * 512];
__device__ uint32_t g_Wl[3][64 * 512];

// split-KV partials (unnormalized O and plain sums l; fixed softmax base 0)
__device__ float g_Opart[Bb * 64 * MAXC * 64 * 64];
__device__ float g_Lpart[Bb * 64 * MAXC * 64];

// ---------------------------------------------------------------------------
__device__ __forceinline__ void mma_bf16(float c[4], uint32_t a0, uint32_t a1,
                                         uint32_t a2, uint32_t a3,
                                         uint32_t b0, uint32_t b1) {
    asm volatile(
        "mma.sync.aligned.m16n8k16.row.col.f32.bf16.bf16.f32 "
        "{%0,%1,%2,%3}, {%4,%5,%6,%7}, {%8,%9}, {%0,%1,%2,%3};"
        : "+f"(c[0]), "+f"(c[1]), "+f"(c[2]), "+f"(c[3])
        : "r"(a0), "r"(a1), "r"(a2), "r"(a3), "r"(b0), "r"(b1));
}

__device__ __forceinline__ void ldmatrix_x4_trans(uint32_t& r0, uint32_t& r1,
                                                  uint32_t& r2, uint32_t& r3,
                                                  uint32_t addr) {
    asm volatile(
        "ldmatrix.sync.aligned.m8n8.x4.trans.shared.b16 {%0,%1,%2,%3}, [%4];"
        : "=r"(r0), "=r"(r1), "=r"(r2), "=r"(r3) : "r"(addr));
}

__device__ __forceinline__ float ex2(float x) {
    float r;
    asm("ex2.approx.ftz.f32 %0, %1;" : "=f"(r) : "f"(x));
    return r;
}

__device__ __forceinline__ uint32_t packbf(float a, float b) {
    __nv_bfloat162 t;
    t.x = __float2bfloat16(a);
    t.y = __float2bfloat16(b);
    return *reinterpret_cast<uint32_t*>(&t);
}

__device__ __forceinline__ void cvt_hilo(float2 v, uint32_t& hi, uint32_t& lo) {
    asm("cvt.rn.bf16x2.f32 %0, %1, %2;" : "=r"(hi) : "f"(v.y), "f"(v.x));
    __nv_bfloat162 h = *reinterpret_cast<__nv_bfloat162*>(&hi);
    float lx = v.x - __bfloat162float(h.x);
    float ly = v.y - __bfloat162float(h.y);
    asm("cvt.rn.bf16x2.f32 %0, %1, %2;" : "=r"(lo) : "f"(ly), "f"(lx));
}

__device__ __forceinline__ void cp16(uint32_t saddr, const void* gaddr) {
    asm volatile("cp.async.cg.shared.global [%0], [%1], 16;"
                 :: "r"(saddr), "l"(gaddr) : "memory");
}
#define CP_COMMIT() asm volatile("cp.async.commit_group;" ::: "memory")
#define CP_WAIT0()  asm volatile("cp.async.wait_group 0;" ::: "memory")

__device__ __forceinline__ uint32_t smem_u32(const void* p) {
    uint32_t a;
    asm("{ .reg .u64 t; cvta.to.shared.u64 t, %1; cvt.u32.u64 %0, t; }"
        : "=r"(a) : "l"(p));
    return a;
}

#define LDF 72   // fp32 row stride for proj X smem
#define LWW 36   // uint32 (bf16x2) row stride (=144B)

// ===========================================================================
// Pre-convert W matrices to bf16 hi/lo packed images.
// ===========================================================================
__global__ __launch_bounds__(128) void wcvt_kernel(
    const float* __restrict__ Wq, const float* __restrict__ Wk,
    const float* __restrict__ Wv)
{
    const int z = blockIdx.y;
    const float* W = (z == 0) ? Wq : (z == 1) ? Wk : Wv;
    uint32_t* outh = g_Wh[z];
    uint32_t* outl = g_Wl[z];
    const int base = blockIdx.x * 2048;
    for (int i = threadIdx.x; i < 2048; i += 128) {
        int w = base + i;
        float2 v = *(const float2*)&W[(long)w * 2];
        uint32_t hi, lo;
        cvt_hilo(v, hi, lo);
        outh[w] = hi;
        outl[w] = lo;
    }
}

// ===========================================================================
// Projection, M=64 per CTA, 3 CTAs/SM, single sync per chunk.
// ===========================================================================
struct PBuf {
    float Xs[64][LDF];         // 18432 B
    uint32_t Whs[64][LWW];     //  9216 B
    uint32_t Wls[64][LWW];     //  9216 B
};                             // 36864 B; x2 = 73728 B

__global__ __launch_bounds__(128, 3) void proj_kernel(
    const float* __restrict__ xq, const float* __restrict__ xk,
    const float* __restrict__ xv)
{
    extern __shared__ char smraw[];
    PBuf* buf = reinterpret_cast<PBuf*>(smraw);

    const float* x;
    const uint32_t* Wh;
    const uint32_t* Wl;
    uint32_t* outh;
    uint32_t* outl;
    if (blockIdx.z == 0)      { x = xq; Wh = g_Wh[0]; Wl = g_Wl[0]; outh = g_Qh; outl = g_Ql; }
    else if (blockIdx.z == 1) { x = xk; Wh = g_Wh[1]; Wl = g_Wl[1]; outh = g_Kh; outl = g_Kl; }
    else                      { x = xv; Wh = g_Wh[2]; Wl = g_Wl[2]; outh = g_Vh; outl = g_Vl; }

    const int tid = threadIdx.x;
    const int warp = tid >> 5;
    const int lane = tid & 31;
    const int lr = lane >> 2;
    const int ql = lane & 3;
    const long row0 = (long)blockIdx.x * 64;

    float acc[8][4];
#pragma unroll
    for (int n = 0; n < 8; n++)
#pragma unroll
        for (int e = 0; e < 4; e++) acc[n][e] = 0.f;

    {
        const uint32_t xb = smem_u32(&buf[0].Xs[0][0]);
        const uint32_t whb = smem_u32(&buf[0].Whs[0][0]);
        const uint32_t wlb = smem_u32(&buf[0].Wls[0][0]);
#pragma unroll
        for (int i = 0; i < 8; i++) {
            int idx = tid + i * 128;
            int r = idx >> 4, seg = idx & 15;
            cp16(xb + (uint32_t)(r * LDF + seg * 4) * 4,
                 &x[(row0 + r) * Cc + 0 + seg * 4]);
        }
#pragma unroll
        for (int i = 0; i < 4; i++) {
            int idx = tid + i * 128;
            int r = idx >> 3, seg = idx & 7;
            uint32_t soff = (uint32_t)(r * LWW + seg * 4) * 4;
            cp16(whb + soff, &Wh[(long)r * 512 + 0 + seg * 4]);
            cp16(wlb + soff, &Wl[(long)r * 512 + 0 + seg * 4]);
        }
        CP_COMMIT();
    }

    for (int chunk = 0; chunk < 16; chunk++) {
        const PBuf& cur = buf[chunk & 1];
        CP_WAIT0();
        __syncthreads();   // data landed; all warps done reading the OTHER buf

        if (chunk < 15) {
            const int k0 = (chunk + 1) * 64;
            const int w0 = (chunk + 1) * 32;
            PBuf& nxt = buf[(chunk + 1) & 1];
            const uint32_t xb = smem_u32(&nxt.Xs[0][0]);
            const uint32_t whb = smem_u32(&nxt.Whs[0][0]);
            const uint32_t wlb = smem_u32(&nxt.Wls[0][0]);
#pragma unroll
            for (int i = 0; i < 8; i++) {
                int idx = tid + i * 128;
                int r = idx >> 4, seg = idx & 15;
                cp16(xb + (uint32_t)(r * LDF + seg * 4) * 4,
                     &x[(row0 + r) * Cc + k0 + seg * 4]);
            }
#pragma unroll
            for (int i = 0; i < 4; i++) {
                int idx = tid + i * 128;
                int r = idx >> 3, seg = idx & 7;
                uint32_t soff = (uint32_t)(r * LWW + seg * 4) * 4;
                cp16(whb + soff, &Wh[(long)r * 512 + w0 + seg * 4]);
                cp16(wlb + soff, &Wl[(long)r * 512 + w0 + seg * 4]);
            }
            CP_COMMIT();
        }

        const int r0 = warp * 16;
#pragma unroll
        for (int s = 0; s < 4; s++) {
            const int kk = s * 16 + ql * 2;
            int rr = r0 + lr;
            uint32_t ah0, ah1, ah2, ah3, al0, al1, al2, al3;
            cvt_hilo(*(const float2*)&cur.Xs[rr][kk],         ah0, al0);
            cvt_hilo(*(const float2*)&cur.Xs[rr + 8][kk],     ah1, al1);
            cvt_hilo(*(const float2*)&cur.Xs[rr][kk + 8],     ah2, al2);
            cvt_hilo(*(const float2*)&cur.Xs[rr + 8][kk + 8], ah3, al3);
#pragma unroll
            for (int n = 0; n < 8; n++) {
                const int ww = (n * 8 + lr) * LWW + 8 * s + ql;
                uint32_t bh0 = cur.Whs[0][ww];
                uint32_t bh1 = cur.Whs[0][ww + 4];
                uint32_t bl0 = cur.Wls[0][ww];
                uint32_t bl1 = cur.Wls[0][ww + 4];
                mma_bf16(acc[n], ah0, ah1, ah2, ah3, bh0, bh1);
                mma_bf16(acc[n], ah0, ah1, ah2, ah3, bl0, bl1);
                mma_bf16(acc[n], al0, al1, al2, al3, bh0, bh1);
            }
        }
        // no bottom sync: next iteration's top sync orders reads vs. refill
    }

    {
        long rr = row0 + warp * 16 + lr;
#pragma unroll
        for (int n = 0; n < 8; n++) {
            int wcol = 4 * n + ql;
            uint32_t h0, l0, h1, l1;
            cvt_hilo(make_float2(acc[n][0], acc[n][1]), h0, l0);
            cvt_hilo(make_float2(acc[n][2], acc[n][3]), h1, l1);
            outh[rr * 32 + wcol] = h0;
            outl[rr * 32 + wcol] = l0;
            outh[(rr + 8) * 32 + wcol] = h1;
            outl[(rr + 8) * 32 + wcol] = l1;
        }
    }
}

// ===========================================================================
// Phase 1: split-KV flash attention. Q frags via LDG (L2-resident), KV
// double-buffered smem, 3 CTAs/SM, single sync per tile, fixed softmax base.
// ===========================================================================
struct ABuf {
    uint32_t Kh[64 * LWW];
    uint32_t Kl[64 * LWW];
    uint32_t Vh[64 * LWW];
    uint32_t Vl[64 * LWW];
};                           // 36864 B; x2 = 73728 B

__device__ __forceinline__ void load_tile(uint32_t dstbase,
                                          const uint32_t* __restrict__ src,
                                          long rowbase, int tid) {
#pragma unroll
    for (int i = 0; i < 4; i++) {
        int idx = tid + i * 128;
        int r = idx >> 3, seg = idx & 7;
        cp16(dstbase + (uint32_t)(r * LWW + seg * 4) * 4,
             &src[(rowbase + r) * 32 + seg * 4]);
    }
}

__global__ __launch_bounds__(128, 3) void attn_kernel()
{
    extern __shared__ char smraw2[];
    ABuf* bufs = reinterpret_cast<ABuf*>(smraw2);

    const int tid = threadIdx.x;
    const int warp = tid >> 5;
    const int lane = tid & 31;
    const int lr = lane >> 2;
    const int lc = (lane & 3) * 2;
    const int ql = lane & 3;
    const int bb = blockIdx.y;

    int rem = blockIdx.x;
    int tq = 0;
#pragma unroll 1
    for (; tq < 64; tq++) {
        int nt = min(tq + 2, 64);
        int nc = (nt + CHUNK - 1) >> 3;
        if (rem < nc) break;
        rem -= nc;
    }
    const int c = rem;
    const int q0 = tq * 64;
    const int ntiles = min(tq + 2, Tt / 64);
    const int tstart = c * CHUNK;
    const int tend = min(tstart + CHUNK, ntiles);

    const long brow = (long)bb * Tt;

    // issue first K/V tile
    {
        const long j0 = (long)tstart * 64;
        load_tile(smem_u32(bufs[0].Kh), g_Kh, brow + j0, tid);
        load_tile(smem_u32(bufs[0].Kl), g_Kl, brow + j0, tid);
        load_tile(smem_u32(bufs[0].Vh), g_Vh, brow + j0, tid);
        load_tile(smem_u32(bufs[0].Vl), g_Vl, brow + j0, tid);
        CP_COMMIT();
    }

    const int qrow = warp * 16 + lr;

    // Q fragments: direct global loads (once per CTA; L2-resident)
    uint32_t qah[4][4], qal[4][4];
    {
        const long qg0 = (brow + q0 + qrow) * 32;
        const long qg8 = qg0 + 8 * 32;
#pragma unroll
        for (int s = 0; s < 4; s++) {
            const int col = 8 * s + ql;
            qah[s][0] = g_Qh[qg0 + col];
            qah[s][1] = g_Qh[qg8 + col];
            qah[s][2] = g_Qh[qg0 + col + 4];
            qah[s][3] = g_Qh[qg8 + col + 4];
            qal[s][0] = g_Ql[qg0 + col];
            qal[s][1] = g_Ql[qg8 + col];
            qal[s][2] = g_Ql[qg0 + col + 4];
            qal[s][3] = g_Ql[qg8 + col + 4];
        }
    }

    float l0 = 0.f, l1 = 0.f;
    float oacc[8][4];
#pragma unroll
    for (int n = 0; n < 8; n++)
#pragma unroll
        for (int e = 0; e < 4; e++) oacc[n][e] = 0.f;

    const uint32_t vofs = (uint32_t)((((lane >> 3) & 1) * 8 + (lane & 7)) * 144 +
                                     ((lane >> 4) * 16));

    for (int t = tstart; t < tend; t++) {
        const int j0 = t * 64;
        const ABuf& cur = bufs[(t - tstart) & 1];
        CP_WAIT0();
        __syncthreads();   // tile landed; all warps done reading the OTHER buf

        if (t + 1 < tend) {
            const long j1 = (long)(t + 1) * 64;
            ABuf& nxt = bufs[(t + 1 - tstart) & 1];
            load_tile(smem_u32(nxt.Kh), g_Kh, brow + j1, tid);
            load_tile(smem_u32(nxt.Kl), g_Kl, brow + j1, tid);
            load_tile(smem_u32(nxt.Vh), g_Vh, brow + j1, tid);
            load_tile(smem_u32(nxt.Vl), g_Vl, brow + j1, tid);
            CP_COMMIT();
        }

        // ---- S = Q K^T (bf16x3) ----
        float sc[8][4];
#pragma unroll
        for (int n = 0; n < 8; n++)
#pragma unroll
            for (int e = 0; e < 4; e++) sc[n][e] = 0.f;
#pragma unroll
        for (int s = 0; s < 4; s++) {
#pragma unroll
            for (int n = 0; n < 8; n++) {
                const int kw = (n * 8 + lr) * LWW + 8 * s + ql;
                uint32_t bh0 = cur.Kh[kw];
                uint32_t bh1 = cur.Kh[kw + 4];
                uint32_t bl0 = cur.Kl[kw];
                uint32_t bl1 = cur.Kl[kw + 4];
                mma_bf16(sc[n], qah[s][0], qah[s][1], qah[s][2], qah[s][3], bh0, bh1);
                mma_bf16(sc[n], qah[s][0], qah[s][1], qah[s][2], qah[s][3], bl0, bl1);
                mma_bf16(sc[n], qal[s][0], qal[s][1], qal[s][2], qal[s][3], bh0, bh1);
            }
        }

        // ---- causal mask (diag offset +1) ----
        if (j0 >= q0) {
            const int i0 = q0 + qrow;
#pragma unroll
            for (int n = 0; n < 8; n++) {
                int j = j0 + n * 8 + lc;
                if (j     > i0 + 1) sc[n][0] = -3.0e38f;
                if (j + 1 > i0 + 1) sc[n][1] = -3.0e38f;
                if (j     > i0 + 9) sc[n][2] = -3.0e38f;
                if (j + 1 > i0 + 9) sc[n][3] = -3.0e38f;
            }
        }

        // ---- softmax numerator, fixed base 0 ----
        float ps0 = 0.f, ps1 = 0.f;
#pragma unroll
        for (int n = 0; n < 8; n++) {
            sc[n][0] = ex2(sc[n][0] * S2L2E);
            sc[n][1] = ex2(sc[n][1] * S2L2E);
            sc[n][2] = ex2(sc[n][2] * S2L2E);
            sc[n][3] = ex2(sc[n][3] * S2L2E);
            ps0 += sc[n][0] + sc[n][1];
            ps1 += sc[n][2] + sc[n][3];
        }
        ps0 += __shfl_xor_sync(0xffffffffu, ps0, 1);
        ps0 += __shfl_xor_sync(0xffffffffu, ps0, 2);
        ps1 += __shfl_xor_sync(0xffffffffu, ps1, 1);
        ps1 += __shfl_xor_sync(0xffffffffu, ps1, 2);
        l0 += ps0;
        l1 += ps1;

        // ---- O += P V (bf16x3) ----
        const uint32_t vhb = smem_u32(cur.Vh) + vofs;
        const uint32_t vlb = smem_u32(cur.Vl) + vofs;
#pragma unroll
        for (int s = 0; s < 4; s++) {
            const int t0 = 2 * s, t1 = 2 * s + 1;
            uint32_t ph0 = packbf(sc[t0][0], sc[t0][1]);
            uint32_t ph1 = packbf(sc[t0][2], sc[t0][3]);
            uint32_t ph2 = packbf(sc[t1][0], sc[t1][1]);
            uint32_t ph3 = packbf(sc[t1][2], sc[t1][3]);
            __nv_bfloat162* hp;
            uint32_t pl0, pl1, pl2, pl3;
            hp = (__nv_bfloat162*)&ph0;
            pl0 = packbf(sc[t0][0] - __bfloat162float(hp->x),
                         sc[t0][1] - __bfloat162float(hp->y));
            hp = (__nv_bfloat162*)&ph1;
            pl1 = packbf(sc[t0][2] - __bfloat162float(hp->x),
                         sc[t0][3] - __bfloat162float(hp->y));
            hp = (__nv_bfloat162*)&ph2;
            pl2 = packbf(sc[t1][0] - __bfloat162float(hp->x),
                         sc[t1][1] - __bfloat162float(hp->y));
            hp = (__nv_bfloat162*)&ph3;
            pl3 = packbf(sc[t1][2] - __bfloat162float(hp->x),
                         sc[t1][3] - __bfloat162float(hp->y));
            const uint32_t sb = (uint32_t)(s * 2304);
#pragma unroll
            for (int np = 0; np < 4; np++) {
                uint32_t bh0, bh1, bh2, bh3, bl0, bl1, bl2, bl3;
                ldmatrix_x4_trans(bh0, bh1, bh2, bh3, vhb + sb + np * 32);
                ldmatrix_x4_trans(bl0, bl1, bl2, bl3, vlb + sb + np * 32);
                mma_bf16(oacc[2 * np],     ph0, ph1, ph2, ph3, bh0, bh1);
                mma_bf16(oacc[2 * np],     ph0, ph1, ph2, ph3, bl0, bl1);
                mma_bf16(oacc[2 * np],     pl0, pl1, pl2, pl3, bh0, bh1);
                mma_bf16(oacc[2 * np + 1], ph0, ph1, ph2, ph3, bh2, bh3);
                mma_bf16(oacc[2 * np + 1], ph0, ph1, ph2, ph3, bl2, bl3);
                mma_bf16(oacc[2 * np + 1], pl0, pl1, pl2, pl3, bh2, bh3);
            }
        }
        // no bottom sync: next iteration's top sync orders reads vs. refill
    }

    const long pbase = (((long)bb * 64 + tq) * MAXC + c) * 64;
    float* Op = g_Opart + pbase * 64;
#pragma unroll
    for (int n = 0; n < 8; n++) {
        int col = n * 8 + lc;
        *(float2*)&Op[(long)qrow * 64 + col] = make_float2(oacc[n][0], oacc[n][1]);
        *(float2*)&Op[(long)(qrow + 8) * 64 + col] = make_float2(oacc[n][2], oacc[n][3]);
    }
    if ((lane & 3) == 0) {
        g_Lpart[pbase + qrow] = l0;
        g_Lpart[pbase + qrow + 8] = l1;
    }
}

// ===========================================================================
// Phase 2: merge = plain sums.
// ===========================================================================
__global__ __launch_bounds__(512) void merge_kernel(float* __restrict__ out)
{
    const int tid = threadIdx.x;
    const int r = tid >> 3;
    const int cg = (tid & 7) * 8;
    const int tq = blockIdx.x;
    const int bb = blockIdx.y;

    const int ntiles = min(tq + 2, Tt / 64);
    const int nc = (ntiles + CHUNK - 1) >> 3;
    const long base = ((long)bb * 64 + tq) * MAXC;

    float acc[8];
#pragma unroll
    for (int i = 0; i < 8; i++) acc[i] = 0.f;
    float ltot = 0.f;

    for (int c = 0; c < nc; c++) {
        ltot += g_Lpart[(base + c) * 64 + r];
        const float* Op = g_Opart + ((base + c) * 64 + r) * 64 + cg;
        float4 v0 = *(const float4*)&Op[0];
        float4 v1 = *(const float4*)&Op[4];
        acc[0] += v0.x; acc[1] += v0.y; acc[2] += v0.z; acc[3] += v0.w;
        acc[4] += v1.x; acc[5] += v1.y; acc[6] += v1.z; acc[7] += v1.w;
    }

    const float inv = 1.0f / ltot;
    float* orow = out + ((long)bb * Tt + tq * 64 + r) * Hh + cg;
    float4 o0, o1;
    o0.x = acc[0] * inv; o0.y = acc[1] * inv;
    o0.z = acc[2] * inv; o0.w = acc[3] * inv;
    o1.x = acc[4] * inv; o1.y = acc[5] * inv;
    o1.z = acc[6] * inv; o1.w = acc[7] * inv;
    *(float4*)&orow[0] = o0;
    *(float4*)&orow[4] = o1;
}

// ===========================================================================
extern "C" void kernel_launch(void* const* d_in, const int* in_sizes, int n_in,
                              void* d_out, int out_size)
{
    const float* q  = (const float*)d_in[0];
    const float* k  = (const float*)d_in[1];
    const float* v  = (const float*)d_in[2];
    const float* Wq = (const float*)d_in[3];
    const float* Wk = (const float*)d_in[4];
    const float* Wv = (const float*)d_in[5];
    float* out = (float*)d_out;

    cudaFuncSetAttribute(proj_kernel,
                         cudaFuncAttributeMaxDynamicSharedMemorySize,
                         (int)(2 * sizeof(PBuf)));
    cudaFuncSetAttribute(attn_kernel,
                         cudaFuncAttributeMaxDynamicSharedMemorySize,
                         (int)(2 * sizeof(ABuf)));

    wcvt_kernel<<<dim3(16, 3), 128>>>(Wq, Wk, Wv);
    dim3 pgrid((Bb * Tt) / 64, 1, 3);
    proj_kernel<<<pgrid, 128, 2 * sizeof(PBuf)>>>(q, k, v);
    attn_kernel<<<dim3(NCHUNKS, Bb), 128, 2 * sizeof(ABuf)>>>();
    merge_kernel<<<dim3(Tt / 64, Bb), 512>>>(out);
}